// round 5
// baseline (speedup 1.0000x reference)
#include <cuda_runtime.h>
#include <math.h>

#define Bnum 32
#define Tnum 2048
#define Hnum 512
#define NBLK 148      // == one CTA per SM -> whole grid resident -> spin barrier safe
#define NTHR 256

// Scratch (static device arrays — allocation-free per harness rules)
__device__ __align__(16) float g_has[Bnum * Hnum];   // ha * 2*log2(e)
__device__ __align__(16) float g_p[Bnum * Tnum];     // unnormalized numerators
__device__ __align__(16) float g_psum[Bnum * 32];    // per-(b,chunk) partials
__device__ unsigned g_bar_count = 0;
__device__ unsigned g_bar_phase = 0;

__device__ __forceinline__ float ex2a(float x) {
    float y; asm("ex2.approx.f32 %0, %1;" : "=f"(y) : "f"(x)); return y;
}
__device__ __forceinline__ float rcpa(float x) {
    float y; asm("rcp.approx.f32 %0, %1;" : "=f"(y) : "f"(x)); return y;
}

#define C2LOG2E 2.8853900817779268f   // 2*log2(e)
#define LOG2E   1.4426950408889634f

// Phase-flip grid barrier. All NBLK blocks are resident (grid == #SMs), so
// spinning cannot deadlock. count is reset by the last arriver; phase
// increments monotonically across barriers/launches (wraps harmlessly).
__device__ __forceinline__ void grid_barrier() {
    __syncthreads();
    if (threadIdx.x == 0) {
        unsigned ph = atomicAdd(&g_bar_phase, 0u);
        __threadfence();
        unsigned old = atomicAdd(&g_bar_count, 1u);
        if (old == NBLK - 1) {
            atomicExch(&g_bar_count, 0u);
            __threadfence();
            atomicExch(&g_bar_phase, ph + 1u);
        } else {
            while (atomicAdd(&g_bar_phase, 0u) == ph) {}
        }
        __threadfence();
    }
    __syncthreads();
}

// ---------------------------------------------------------------------------
// One persistent kernel, three phases separated by grid barriers.
// ---------------------------------------------------------------------------
__global__ __launch_bounds__(NTHR) void fused_kernel(
    const float* __restrict__ hidden,    // [2,B,H]
    const float* __restrict__ eo,        // [T,B,H]
    const int*   __restrict__ enc_len_w, // [B] int32 or int64 (auto-detect)
    const float* __restrict__ Wh,        // [H,H]
    const float* __restrict__ bh,        // [H]
    const float* __restrict__ Wo,        // [1,H]
    float* __restrict__ out)             // [B,T,1]
{
    __shared__ float s_w[2 * Hnum];
    __shared__ float s_ws[8];

    const int tid  = threadIdx.x;
    const int warp = tid >> 5;
    const int lane = tid & 31;

    // ============== Phase 0: ha = (mean_L hidden) @ Wh^T + bh, pre-scaled ====
    // Work item = 2 h-rows; 256 items over NBLK blocks.
    for (int it = blockIdx.x; it < Hnum / 2; it += NBLK) {
        const int h0 = it * 2;
        {   // stage 2 Wh rows (256 float4)
            const float4* __restrict__ w4 = (const float4*)(Wh + (size_t)h0 * Hnum);
            ((float4*)s_w)[tid] = w4[tid];
        }
        __syncthreads();

        const int b0 = warp * 4;
        const float* __restrict__ hA = hidden;                 // layer 0
        const float* __restrict__ hB = hidden + Bnum * Hnum;   // layer 1

        float a00 = 0.f, a01 = 0.f, a02 = 0.f, a03 = 0.f;   // h0
        float a10 = 0.f, a11 = 0.f, a12 = 0.f, a13 = 0.f;   // h0+1
        #pragma unroll
        for (int k = lane; k < Hnum; k += 32) {
            float w0 = s_w[k];
            float w1 = s_w[Hnum + k];
            float v0 = 0.5f * (hA[(b0 + 0) * Hnum + k] + hB[(b0 + 0) * Hnum + k]);
            float v1 = 0.5f * (hA[(b0 + 1) * Hnum + k] + hB[(b0 + 1) * Hnum + k]);
            float v2 = 0.5f * (hA[(b0 + 2) * Hnum + k] + hB[(b0 + 2) * Hnum + k]);
            float v3 = 0.5f * (hA[(b0 + 3) * Hnum + k] + hB[(b0 + 3) * Hnum + k]);
            a00 = fmaf(v0, w0, a00); a01 = fmaf(v1, w0, a01);
            a02 = fmaf(v2, w0, a02); a03 = fmaf(v3, w0, a03);
            a10 = fmaf(v0, w1, a10); a11 = fmaf(v1, w1, a11);
            a12 = fmaf(v2, w1, a12); a13 = fmaf(v3, w1, a13);
        }
        #pragma unroll
        for (int off = 16; off; off >>= 1) {
            a00 += __shfl_xor_sync(0xffffffffu, a00, off);
            a01 += __shfl_xor_sync(0xffffffffu, a01, off);
            a02 += __shfl_xor_sync(0xffffffffu, a02, off);
            a03 += __shfl_xor_sync(0xffffffffu, a03, off);
            a10 += __shfl_xor_sync(0xffffffffu, a10, off);
            a11 += __shfl_xor_sync(0xffffffffu, a11, off);
            a12 += __shfl_xor_sync(0xffffffffu, a12, off);
            a13 += __shfl_xor_sync(0xffffffffu, a13, off);
        }
        if (lane == 0) {
            const float b_h0 = bh[h0], b_h1 = bh[h0 + 1];
            g_has[(b0 + 0) * Hnum + h0]     = (a00 + b_h0) * C2LOG2E;
            g_has[(b0 + 1) * Hnum + h0]     = (a01 + b_h0) * C2LOG2E;
            g_has[(b0 + 2) * Hnum + h0]     = (a02 + b_h0) * C2LOG2E;
            g_has[(b0 + 3) * Hnum + h0]     = (a03 + b_h0) * C2LOG2E;
            g_has[(b0 + 0) * Hnum + h0 + 1] = (a10 + b_h1) * C2LOG2E;
            g_has[(b0 + 1) * Hnum + h0 + 1] = (a11 + b_h1) * C2LOG2E;
            g_has[(b0 + 2) * Hnum + h0 + 1] = (a12 + b_h1) * C2LOG2E;
            g_has[(b0 + 3) * Hnum + h0 + 1] = (a13 + b_h1) * C2LOG2E;
        }
        __syncthreads();
    }

    grid_barrier();

    // ============== Phase 1: p = exp(energy) with ragged skip ===============
    // enc_len dtype auto-detect: lengths >= 1, so word[1]==0 iff int64.
    const bool is64 = (enc_len_w[1] == 0);

    // Wo held in registers for the whole phase (lane-sliced float4 x4).
    const float4* __restrict__ wo4 = (const float4*)Wo;
    float4 wo[4];
    #pragma unroll
    for (int j = 0; j < 4; j++) wo[j] = wo4[j * 32 + lane];

    const float4* __restrict__ eo4 = (const float4*)eo;

    // Work item = (b, 64-t chunk); 1024 items, b-major interleave for balance.
    for (int it = blockIdx.x; it < Bnum * 32; it += NBLK) {
        const int b = it & 31;
        const int chunk = it >> 5;
        const int tbase = chunk * 64;
        const int len = is64 ? enc_len_w[2 * b] : enc_len_w[b];

        if (tbase >= len) {   // fully masked: zeros, no eo traffic
            if (tid < 16) ((float4*)&g_p[b * Tnum + tbase])[tid] =
                make_float4(0.f, 0.f, 0.f, 0.f);
            if (tid == 0) g_psum[b * 32 + chunk] = 0.f;
            continue;
        }

        // ha slice for this b, lane-sliced into registers (L2-hot, 2KB/warp)
        const float4* __restrict__ ha4 = (const float4*)(g_has + b * Hnum);
        float4 hs[4];
        #pragma unroll
        for (int j = 0; j < 4; j++) hs[j] = ha4[j * 32 + lane];

        float wsum = 0.f;
        #pragma unroll 2
        for (int i = 0; i < 8; i++) {
            const int t = tbase + warp * 8 + i;
            if (t < len) {
                const size_t base = ((size_t)t * Bnum + b) * (Hnum / 4);
                float acc = 0.f;
                #pragma unroll
                for (int j = 0; j < 4; j++) {
                    float4 e = __ldcs(&eo4[base + j * 32 + lane]);
                    float arg, ex;
                    arg = fmaf(e.x, C2LOG2E, hs[j].x);
                    arg = fminf(fmaxf(arg, -80.f), 80.f);
                    ex  = ex2a(arg);
                    acc = fmaf((ex - 1.f) * wo[j].x, rcpa(ex + 1.f), acc);

                    arg = fmaf(e.y, C2LOG2E, hs[j].y);
                    arg = fminf(fmaxf(arg, -80.f), 80.f);
                    ex  = ex2a(arg);
                    acc = fmaf((ex - 1.f) * wo[j].y, rcpa(ex + 1.f), acc);

                    arg = fmaf(e.z, C2LOG2E, hs[j].z);
                    arg = fminf(fmaxf(arg, -80.f), 80.f);
                    ex  = ex2a(arg);
                    acc = fmaf((ex - 1.f) * wo[j].z, rcpa(ex + 1.f), acc);

                    arg = fmaf(e.w, C2LOG2E, hs[j].w);
                    arg = fminf(fmaxf(arg, -80.f), 80.f);
                    ex  = ex2a(arg);
                    acc = fmaf((ex - 1.f) * wo[j].w, rcpa(ex + 1.f), acc);
                }
                #pragma unroll
                for (int off = 16; off; off >>= 1)
                    acc += __shfl_xor_sync(0xffffffffu, acc, off);
                // no-max exp is safe: |energy| <= sum|Wo| ~ 18 << fp32 range
                float p = ex2a(acc * LOG2E);
                if (lane == 0) {
                    g_p[b * Tnum + t] = p;
                    wsum += p;
                }
            } else if (lane == 0) {
                g_p[b * Tnum + t] = 0.f;
            }
        }
        if (lane == 0) s_ws[warp] = wsum;
        __syncthreads();
        if (tid == 0) {
            float tot = 0.f;
            #pragma unroll
            for (int i = 0; i < 8; i++) tot += s_ws[i];
            g_psum[b * 32 + chunk] = tot;
        }
        __syncthreads();   // protect s_ws before next item
    }

    grid_barrier();

    // ============== Phase 2: normalize (64 blocks, L2-hot) ==================
    if (blockIdx.x < 64) {
        const int b = blockIdx.x >> 1;
        const int half = blockIdx.x & 1;

        // every warp redundantly reduces the 32 partials for b (L1-hot)
        float v = g_psum[b * 32 + lane];
        #pragma unroll
        for (int off = 16; off; off >>= 1)
            v += __shfl_xor_sync(0xffffffffu, v, off);
        const float rinv = 1.0f / v;

        const int idx = b * (Tnum / 4) + half * 256 + tid;   // float4 index
        float4 p = ((const float4*)g_p)[idx];
        float4 o;
        o.x = p.x * rinv; o.y = p.y * rinv; o.z = p.z * rinv; o.w = p.w * rinv;
        ((float4*)out)[idx] = o;
    }
}

// ---------------------------------------------------------------------------
extern "C" void kernel_launch(void* const* d_in, const int* in_sizes, int n_in,
                              void* d_out, int out_size)
{
    const float* hidden  = (const float*)d_in[0];      // [L,B,H]
    const float* eo      = (const float*)d_in[1];      // [T,B,H]
    const int*   enc_len = (const int*)d_in[2];        // [B] int32/int64
    const float* Wh      = (const float*)d_in[3];      // [H,H]
    const float* bh      = (const float*)d_in[4];      // [H]
    const float* Wo      = (const float*)d_in[5];      // [1,H]
    // d_in[6] = bo: uniform additive constant -> cancels in softmax, unused.
    float* out = (float*)d_out;                         // [B,T,1]

    fused_kernel<<<NBLK, NTHR>>>(hidden, eo, enc_len, Wh, bh, Wo, out);
}

// round 6
// speedup vs baseline: 1.4010x; 1.4010x over previous
#include <cuda_runtime.h>
#include <math.h>

#define Bnum 32
#define Tnum 2048
#define Hnum 512

// Scratch (static device arrays — allocation-free per harness rules)
__device__ __align__(16) float g_has[Bnum * Hnum];   // ha * 2*log2(e)
__device__ __align__(16) float g_p[Bnum * Tnum];     // unnormalized numerators
__device__ __align__(16) float g_psum[Bnum * 32];    // per-(b,chunk) partials
__device__ unsigned g_done[Bnum];                    // zero-init; reset each use

__device__ __forceinline__ float ex2a(float x) {
    float y; asm("ex2.approx.f32 %0, %1;" : "=f"(y) : "f"(x)); return y;
}
__device__ __forceinline__ float rcpa(float x) {
    float y; asm("rcp.approx.f32 %0, %1;" : "=f"(y) : "f"(x)); return y;
}

#define C2LOG2E 2.8853900817779268f   // 2*log2(e)
#define LOG2E   1.4426950408889634f

// ---------------------------------------------------------------------------
// Kernel A: ha[b,h] = sum_k mean_L(hidden)[b,k]*Wh[h,k] + bh[h], pre-scaled.
// Mean fused inline (hidden is 256KB, L2-resident). 64 blocks x 8 h-rows;
// warp handles 4 b x 8 h = 32 accumulators in one 16-iter k-loop.
// ---------------------------------------------------------------------------
__global__ __launch_bounds__(256) void proj_kernel(
    const float* __restrict__ hidden,
    const float* __restrict__ Wh,
    const float* __restrict__ bh)
{
    const int h0 = blockIdx.x * 8;
    __shared__ float s_w[8 * Hnum];   // 16KB
    {
        const float4* __restrict__ w4 = (const float4*)(Wh + (size_t)h0 * Hnum);
        for (int i = threadIdx.x; i < 8 * Hnum / 4; i += 256)
            ((float4*)s_w)[i] = w4[i];
    }
    __syncthreads();

    const int warp = threadIdx.x >> 5;
    const int lane = threadIdx.x & 31;
    const int b0 = warp * 4;
    const float* __restrict__ hA = hidden;                 // layer 0
    const float* __restrict__ hB = hidden + Bnum * Hnum;   // layer 1

    float acc[8][4];
    #pragma unroll
    for (int h = 0; h < 8; h++)
        #pragma unroll
        for (int j = 0; j < 4; j++) acc[h][j] = 0.f;

    #pragma unroll
    for (int k = lane; k < Hnum; k += 32) {
        float v0 = 0.5f * (hA[(b0 + 0) * Hnum + k] + hB[(b0 + 0) * Hnum + k]);
        float v1 = 0.5f * (hA[(b0 + 1) * Hnum + k] + hB[(b0 + 1) * Hnum + k]);
        float v2 = 0.5f * (hA[(b0 + 2) * Hnum + k] + hB[(b0 + 2) * Hnum + k]);
        float v3 = 0.5f * (hA[(b0 + 3) * Hnum + k] + hB[(b0 + 3) * Hnum + k]);
        #pragma unroll
        for (int h = 0; h < 8; h++) {
            float w = s_w[h * Hnum + k];
            acc[h][0] = fmaf(v0, w, acc[h][0]);
            acc[h][1] = fmaf(v1, w, acc[h][1]);
            acc[h][2] = fmaf(v2, w, acc[h][2]);
            acc[h][3] = fmaf(v3, w, acc[h][3]);
        }
    }
    #pragma unroll
    for (int h = 0; h < 8; h++)
        #pragma unroll
        for (int j = 0; j < 4; j++) {
            float a = acc[h][j];
            #pragma unroll
            for (int off = 16; off; off >>= 1)
                a += __shfl_xor_sync(0xffffffffu, a, off);
            acc[h][j] = a;
        }
    if (lane == 0) {
        #pragma unroll
        for (int h = 0; h < 8; h++) {
            float bhv = bh[h0 + h];
            #pragma unroll
            for (int j = 0; j < 4; j++)
                g_has[(b0 + j) * Hnum + h0 + h] = (acc[h][j] + bhv) * C2LOG2E;
        }
    }
}

// ---------------------------------------------------------------------------
// Kernel B: p[b,t] = exp( sum_h Wo[h]*tanh(eo[t,b,h]+ha[b,h]) ) for t<len,
// else 0, PLUS fused normalization: the last-finishing chunk-block of each b
// (threadfence-reduction pattern) reduces the 32 deterministic partial sums
// and writes out[b,:] = p/sum. Ragged skip: eo rows for t>=len never loaded.
// No-max exp is safe: |energy| <= sum|Wo| ~ 18 << fp32 exp range.
// ---------------------------------------------------------------------------
__global__ __launch_bounds__(256) void energy_kernel(
    const float* __restrict__ eo,
    const float* __restrict__ Wo,
    const int*   __restrict__ enc_len_w,
    float* __restrict__ out)
{
    const int b = blockIdx.y;
    const int chunk = blockIdx.x;
    const int tbase = chunk * 64;
    // enc_len dtype auto-detect (JAX may canonicalize int64->int32):
    // lengths >= 1, so word[1]==0 iff buffer is little-endian int64.
    const bool is64 = (enc_len_w[1] == 0);
    const int len = is64 ? enc_len_w[2 * b] : enc_len_w[b];

    __shared__ float s_has[Hnum];
    __shared__ float s_wo[Hnum];
    __shared__ float s_ws[8];
    __shared__ float s_rinv;
    __shared__ int   s_last;

    const int tid  = threadIdx.x;
    const int warp = tid >> 5;
    const int lane = tid & 31;

    if (tbase < len) {
        for (int i = tid; i < Hnum; i += 256) {
            s_has[i] = g_has[b * Hnum + i];
            s_wo[i]  = Wo[i];
        }
        __syncthreads();

        const float4* __restrict__ eo4 = (const float4*)eo;
        float wsum = 0.f;
        #pragma unroll 2
        for (int i = 0; i < 8; i++) {
            const int t = tbase + warp * 8 + i;
            if (t < len) {
                const size_t base = ((size_t)t * Bnum + b) * (Hnum / 4);
                float acc = 0.f;
                #pragma unroll
                for (int j = 0; j < 4; j++) {
                    const int k4 = j * 32 + lane;
                    float4 e  = __ldcs(&eo4[base + k4]);
                    float4 hs = *(const float4*)&s_has[k4 * 4];
                    float4 wo = *(const float4*)&s_wo[k4 * 4];

                    float arg, ex;
                    arg = fmaf(e.x, C2LOG2E, hs.x);
                    arg = fminf(fmaxf(arg, -80.f), 80.f);
                    ex  = ex2a(arg);
                    acc = fmaf((ex - 1.f) * wo.x, rcpa(ex + 1.f), acc);

                    arg = fmaf(e.y, C2LOG2E, hs.y);
                    arg = fminf(fmaxf(arg, -80.f), 80.f);
                    ex  = ex2a(arg);
                    acc = fmaf((ex - 1.f) * wo.y, rcpa(ex + 1.f), acc);

                    arg = fmaf(e.z, C2LOG2E, hs.z);
                    arg = fminf(fmaxf(arg, -80.f), 80.f);
                    ex  = ex2a(arg);
                    acc = fmaf((ex - 1.f) * wo.z, rcpa(ex + 1.f), acc);

                    arg = fmaf(e.w, C2LOG2E, hs.w);
                    arg = fminf(fmaxf(arg, -80.f), 80.f);
                    ex  = ex2a(arg);
                    acc = fmaf((ex - 1.f) * wo.w, rcpa(ex + 1.f), acc);
                }
                #pragma unroll
                for (int off = 16; off; off >>= 1)
                    acc += __shfl_xor_sync(0xffffffffu, acc, off);
                float p = ex2a(acc * LOG2E);     // exp(energy), no-max
                if (lane == 0) {
                    g_p[b * Tnum + t] = p;
                    wsum += p;
                }
            } else if (lane == 0) {
                g_p[b * Tnum + t] = 0.f;
            }
        }
        if (lane == 0) s_ws[warp] = wsum;
        __syncthreads();
        if (tid == 0) {
            float tot = 0.f;
            #pragma unroll
            for (int i = 0; i < 8; i++) tot += s_ws[i];
            g_psum[b * 32 + chunk] = tot;
        }
    } else {
        // fully masked chunk: zeros, no eo traffic
        if (tid < 16)
            ((float4*)&g_p[b * Tnum + tbase])[tid] = make_float4(0.f, 0.f, 0.f, 0.f);
        if (tid == 0) g_psum[b * 32 + chunk] = 0.f;
    }

    // ---- threadfence-reduction handoff: last block of this b normalizes ----
    __threadfence();
    if (tid == 0)
        s_last = (atomicAdd(&g_done[b], 1u) == 31u);
    __syncthreads();
    if (!s_last) return;

    if (tid < 32) {
        float v = g_psum[b * 32 + tid];
        #pragma unroll
        for (int off = 16; off; off >>= 1)
            v += __shfl_xor_sync(0xffffffffu, v, off);
        if (tid == 0) s_rinv = 1.0f / v;
    }
    __syncthreads();
    const float rinv = s_rinv;

    const float4* __restrict__ p4 = (const float4*)&g_p[b * Tnum];
    float4* __restrict__ o4 = (float4*)&out[b * Tnum];
    #pragma unroll 2
    for (int i = tid; i < Tnum / 4; i += 256) {
        float4 p = p4[i];
        float4 o;
        o.x = p.x * rinv; o.y = p.y * rinv; o.z = p.z * rinv; o.w = p.w * rinv;
        o4[i] = o;
    }
    if (tid == 0) g_done[b] = 0u;   // reset for next graph replay
}

// ---------------------------------------------------------------------------
extern "C" void kernel_launch(void* const* d_in, const int* in_sizes, int n_in,
                              void* d_out, int out_size)
{
    const float* hidden  = (const float*)d_in[0];      // [L,B,H]
    const float* eo      = (const float*)d_in[1];      // [T,B,H]
    const int*   enc_len = (const int*)d_in[2];        // [B] int32/int64 (auto-detect)
    const float* Wh      = (const float*)d_in[3];      // [H,H]
    const float* bh      = (const float*)d_in[4];      // [H]
    const float* Wo      = (const float*)d_in[5];      // [1,H]
    // d_in[6] = bo: uniform additive constant -> cancels in softmax, unused.
    float* out = (float*)d_out;                         // [B,T,1]

    proj_kernel<<<Hnum / 8, 256>>>(hidden, Wh, bh);
    energy_kernel<<<dim3(32, Bnum), 256>>>(eo, Wo, enc_len, out);
}

// round 7
// speedup vs baseline: 1.7446x; 1.2452x over previous
#include <cuda_runtime.h>
#include <math.h>

#define Bnum 32
#define Tnum 2048
#define Hnum 512
#define CHUNK 32                    // t-rows per energy block
#define NCHUNK (Tnum / CHUNK)       // 64 chunks per b

// Scratch (static device arrays — allocation-free per harness rules)
__device__ __align__(16) float g_has[Bnum * Hnum];     // ha (unscaled)
__device__ __align__(16) float g_p[Bnum * Tnum];       // unnormalized numerators
__device__ __align__(16) float g_psum[Bnum * NCHUNK];  // per-(b,chunk) partials
__device__ unsigned g_done[Bnum];                      // zero-init; reset each use

__device__ __forceinline__ float ex2a(float x) {
    float y; asm("ex2.approx.f32 %0, %1;" : "=f"(y) : "f"(x)); return y;
}
__device__ __forceinline__ float tanha(float x) {
    float y; asm("tanh.approx.f32 %0, %1;" : "=f"(y) : "f"(x)); return y;
}

#define LOG2E 1.4426950408889634f

// ---------------------------------------------------------------------------
// Kernel A: ha[b,h] = sum_k mean_L(hidden)[b,k]*Wh[h,k] + bh[h].
// Mean fused inline (hidden is 256KB, L2-resident). 64 blocks x 8 h-rows;
// warp handles 4 b x 8 h = 32 accumulators in one 16-iter k-loop.
// ---------------------------------------------------------------------------
__global__ __launch_bounds__(256) void proj_kernel(
    const float* __restrict__ hidden,
    const float* __restrict__ Wh,
    const float* __restrict__ bh)
{
    const int h0 = blockIdx.x * 8;
    __shared__ float s_w[8 * Hnum];   // 16KB
    {
        const float4* __restrict__ w4 = (const float4*)(Wh + (size_t)h0 * Hnum);
        for (int i = threadIdx.x; i < 8 * Hnum / 4; i += 256)
            ((float4*)s_w)[i] = w4[i];
    }
    __syncthreads();

    const int warp = threadIdx.x >> 5;
    const int lane = threadIdx.x & 31;
    const int b0 = warp * 4;
    const float* __restrict__ hA = hidden;                 // layer 0
    const float* __restrict__ hB = hidden + Bnum * Hnum;   // layer 1

    float acc[8][4];
    #pragma unroll
    for (int h = 0; h < 8; h++)
        #pragma unroll
        for (int j = 0; j < 4; j++) acc[h][j] = 0.f;

    #pragma unroll
    for (int k = lane; k < Hnum; k += 32) {
        float v0 = 0.5f * (hA[(b0 + 0) * Hnum + k] + hB[(b0 + 0) * Hnum + k]);
        float v1 = 0.5f * (hA[(b0 + 1) * Hnum + k] + hB[(b0 + 1) * Hnum + k]);
        float v2 = 0.5f * (hA[(b0 + 2) * Hnum + k] + hB[(b0 + 2) * Hnum + k]);
        float v3 = 0.5f * (hA[(b0 + 3) * Hnum + k] + hB[(b0 + 3) * Hnum + k]);
        #pragma unroll
        for (int h = 0; h < 8; h++) {
            float w = s_w[h * Hnum + k];
            acc[h][0] = fmaf(v0, w, acc[h][0]);
            acc[h][1] = fmaf(v1, w, acc[h][1]);
            acc[h][2] = fmaf(v2, w, acc[h][2]);
            acc[h][3] = fmaf(v3, w, acc[h][3]);
        }
    }
    #pragma unroll
    for (int h = 0; h < 8; h++)
        #pragma unroll
        for (int j = 0; j < 4; j++) {
            float a = acc[h][j];
            #pragma unroll
            for (int off = 16; off; off >>= 1)
                a += __shfl_xor_sync(0xffffffffu, a, off);
            acc[h][j] = a;
        }
    if (lane == 0) {
        #pragma unroll
        for (int h = 0; h < 8; h++) {
            float bhv = bh[h0 + h];
            #pragma unroll
            for (int j = 0; j < 4; j++)
                g_has[(b0 + j) * Hnum + h0 + h] = acc[h][j] + bhv;
        }
    }
}

// ---------------------------------------------------------------------------
// Kernel B: p[b,t] = exp( sum_h Wo[h]*tanh(eo[t,b,h]+ha[b,h]) ) for t<len,
// else 0, PLUS fused normalization via threadfence-reduction: the 64th
// finishing chunk-block of each b reduces the deterministic partials and
// writes out[b,:] = p/sum. Ragged skip: eo rows for t>=len never loaded.
// tanh.approx.f32: single MUFU op, rel err ~2^-11 -> weight err ~2e-4.
// No-max exp is safe: |energy| <= sum|Wo| ~ 18 << fp32 exp range.
// ---------------------------------------------------------------------------
__global__ __launch_bounds__(256, 8) void energy_kernel(
    const float* __restrict__ eo,
    const float* __restrict__ Wo,
    const int*   __restrict__ enc_len_w,
    float* __restrict__ out)
{
    const int b = blockIdx.y;
    const int chunk = blockIdx.x;
    const int tbase = chunk * CHUNK;
    // enc_len dtype auto-detect (JAX may canonicalize int64->int32):
    // lengths >= 1, so word[1]==0 iff buffer is little-endian int64.
    const bool is64 = (enc_len_w[1] == 0);
    const int len = is64 ? enc_len_w[2 * b] : enc_len_w[b];

    __shared__ float s_has[Hnum];
    __shared__ float s_wo[Hnum];
    __shared__ float s_ws[8];
    __shared__ float s_rinv;
    __shared__ int   s_last;

    const int tid  = threadIdx.x;
    const int warp = tid >> 5;
    const int lane = tid & 31;

    if (tbase < len) {
        for (int i = tid; i < Hnum; i += 256) {
            s_has[i] = g_has[b * Hnum + i];
            s_wo[i]  = Wo[i];
        }
        __syncthreads();

        const float4* __restrict__ eo4 = (const float4*)eo;
        float wsum = 0.f;
        #pragma unroll
        for (int i = 0; i < CHUNK / 8; i++) {
            const int t = tbase + warp * (CHUNK / 8) + i;
            if (t < len) {
                const size_t base = ((size_t)t * Bnum + b) * (Hnum / 4);
                float acc = 0.f;
                #pragma unroll
                for (int j = 0; j < 4; j++) {
                    const int k4 = j * 32 + lane;
                    float4 e  = __ldcs(&eo4[base + k4]);
                    float4 hs = *(const float4*)&s_has[k4 * 4];
                    float4 wo = *(const float4*)&s_wo[k4 * 4];
                    acc = fmaf(tanha(e.x + hs.x), wo.x, acc);
                    acc = fmaf(tanha(e.y + hs.y), wo.y, acc);
                    acc = fmaf(tanha(e.z + hs.z), wo.z, acc);
                    acc = fmaf(tanha(e.w + hs.w), wo.w, acc);
                }
                #pragma unroll
                for (int off = 16; off; off >>= 1)
                    acc += __shfl_xor_sync(0xffffffffu, acc, off);
                float p = ex2a(acc * LOG2E);     // exp(energy), no-max
                if (lane == 0) {
                    g_p[b * Tnum + t] = p;
                    wsum += p;
                }
            } else if (lane == 0) {
                g_p[b * Tnum + t] = 0.f;
            }
        }
        if (lane == 0) s_ws[warp] = wsum;
        __syncthreads();
        if (tid == 0) {
            float tot = 0.f;
            #pragma unroll
            for (int i = 0; i < 8; i++) tot += s_ws[i];
            g_psum[b * NCHUNK + chunk] = tot;
        }
    } else {
        // fully masked chunk: zeros, no eo traffic
        if (tid < CHUNK / 4)
            ((float4*)&g_p[b * Tnum + tbase])[tid] = make_float4(0.f, 0.f, 0.f, 0.f);
        if (tid == 0) g_psum[b * NCHUNK + chunk] = 0.f;
    }

    // ---- threadfence-reduction handoff: last block of this b normalizes ----
    __threadfence();
    if (tid == 0)
        s_last = (atomicAdd(&g_done[b], 1u) == NCHUNK - 1);
    __syncthreads();
    if (!s_last) return;

    if (tid < 64) {
        float v = g_psum[b * NCHUNK + tid] + g_psum[b * NCHUNK + tid + 0];  // placeholder
    }
    if (tid < 32) {
        float v = g_psum[b * NCHUNK + tid] + g_psum[b * NCHUNK + 32 + tid];
        #pragma unroll
        for (int off = 16; off; off >>= 1)
            v += __shfl_xor_sync(0xffffffffu, v, off);
        if (tid == 0) s_rinv = 1.0f / v;
    }
    __syncthreads();
    const float rinv = s_rinv;

    const float4* __restrict__ p4 = (const float4*)&g_p[b * Tnum];
    float4* __restrict__ o4 = (float4*)&out[b * Tnum];
    #pragma unroll 2
    for (int i = tid; i < Tnum / 4; i += 256) {
        float4 p = p4[i];
        float4 o;
        o.x = p.x * rinv; o.y = p.y * rinv; o.z = p.z * rinv; o.w = p.w * rinv;
        o4[i] = o;
    }
    if (tid == 0) g_done[b] = 0u;   // reset for next graph replay
}

// ---------------------------------------------------------------------------
extern "C" void kernel_launch(void* const* d_in, const int* in_sizes, int n_in,
                              void* d_out, int out_size)
{
    const float* hidden  = (const float*)d_in[0];      // [L,B,H]
    const float* eo      = (const float*)d_in[1];      // [T,B,H]
    const int*   enc_len = (const int*)d_in[2];        // [B] int32/int64 (auto-detect)
    const float* Wh      = (const float*)d_in[3];      // [H,H]
    const float* bh      = (const float*)d_in[4];      // [H]
    const float* Wo      = (const float*)d_in[5];      // [1,H]
    // d_in[6] = bo: uniform additive constant -> cancels in softmax, unused.
    float* out = (float*)d_out;                         // [B,T,1]

    proj_kernel<<<Hnum / 8, 256>>>(hidden, Wh, bh);
    energy_kernel<<<dim3(NCHUNK, Bnum), 256>>>(eo, Wo, enc_len, out);
}

// round 8
// speedup vs baseline: 1.8764x; 1.0755x over previous
#include <cuda_runtime.h>
#include <math.h>

#define Bnum 32
#define Tnum 2048
#define Hnum 512
#define CHUNK 16                    // t-rows per energy block (4 warps x 4 rows)
#define NCHUNK (Tnum / CHUNK)       // 128 chunks per b
#define ETHR 128                    // energy block threads

// Scratch (static device arrays — allocation-free per harness rules)
__device__ __align__(16) float g_has[Bnum * Hnum];     // ha (unscaled)
__device__ __align__(16) float g_p[Bnum * Tnum];       // unnormalized numerators
__device__ __align__(16) float g_psum[Bnum * NCHUNK];  // per-(b,chunk) partials
__device__ unsigned g_done[Bnum];                      // zero-init; reset each use

__device__ __forceinline__ float ex2a(float x) {
    float y; asm("ex2.approx.f32 %0, %1;" : "=f"(y) : "f"(x)); return y;
}
__device__ __forceinline__ float tanha(float x) {
    float y; asm("tanh.approx.f32 %0, %1;" : "=f"(y) : "f"(x)); return y;
}

#define LOG2E 1.4426950408889634f

// ---------------------------------------------------------------------------
// Kernel A: ha[b,h] = sum_k mean_L(hidden)[b,k]*Wh[h,k] + bh[h].
// Mean fused inline (hidden is 256KB, L2-resident). 64 blocks x 8 h-rows;
// warp handles 4 b x 8 h = 32 accumulators in one 16-iter k-loop.
// ---------------------------------------------------------------------------
__global__ __launch_bounds__(256) void proj_kernel(
    const float* __restrict__ hidden,
    const float* __restrict__ Wh,
    const float* __restrict__ bh)
{
    const int h0 = blockIdx.x * 8;
    __shared__ float s_w[8 * Hnum];   // 16KB
    {
        const float4* __restrict__ w4 = (const float4*)(Wh + (size_t)h0 * Hnum);
        for (int i = threadIdx.x; i < 8 * Hnum / 4; i += 256)
            ((float4*)s_w)[i] = w4[i];
    }
    __syncthreads();

    const int warp = threadIdx.x >> 5;
    const int lane = threadIdx.x & 31;
    const int b0 = warp * 4;
    const float* __restrict__ hA = hidden;                 // layer 0
    const float* __restrict__ hB = hidden + Bnum * Hnum;   // layer 1

    float acc[8][4];
    #pragma unroll
    for (int h = 0; h < 8; h++)
        #pragma unroll
        for (int j = 0; j < 4; j++) acc[h][j] = 0.f;

    #pragma unroll
    for (int k = lane; k < Hnum; k += 32) {
        float v0 = 0.5f * (hA[(b0 + 0) * Hnum + k] + hB[(b0 + 0) * Hnum + k]);
        float v1 = 0.5f * (hA[(b0 + 1) * Hnum + k] + hB[(b0 + 1) * Hnum + k]);
        float v2 = 0.5f * (hA[(b0 + 2) * Hnum + k] + hB[(b0 + 2) * Hnum + k]);
        float v3 = 0.5f * (hA[(b0 + 3) * Hnum + k] + hB[(b0 + 3) * Hnum + k]);
        #pragma unroll
        for (int h = 0; h < 8; h++) {
            float w = s_w[h * Hnum + k];
            acc[h][0] = fmaf(v0, w, acc[h][0]);
            acc[h][1] = fmaf(v1, w, acc[h][1]);
            acc[h][2] = fmaf(v2, w, acc[h][2]);
            acc[h][3] = fmaf(v3, w, acc[h][3]);
        }
    }
    #pragma unroll
    for (int h = 0; h < 8; h++)
        #pragma unroll
        for (int j = 0; j < 4; j++) {
            float a = acc[h][j];
            #pragma unroll
            for (int off = 16; off; off >>= 1)
                a += __shfl_xor_sync(0xffffffffu, a, off);
            acc[h][j] = a;
        }
    if (lane == 0) {
        #pragma unroll
        for (int h = 0; h < 8; h++) {
            float bhv = bh[h0 + h];
            #pragma unroll
            for (int j = 0; j < 4; j++)
                g_has[(b0 + j) * Hnum + h0 + h] = acc[h][j] + bhv;
        }
    }
}

// ---------------------------------------------------------------------------
// Kernel B: p[b,t] = exp( sum_h Wo[h]*tanh(eo[t,b,h]+ha[b,h]) ) for t<len,
// else 0, PLUS fused normalization via threadfence-reduction.
// Warp processes 4 rows CONCURRENTLY (j-sliced loads, 4 independent acc
// chains, one amortized reduce/exp/store tail) -> ~2x memory-level
// parallelism and 1/4 the serial tail vs row-serial form.
// ---------------------------------------------------------------------------
__global__ __launch_bounds__(ETHR) void energy_kernel(
    const float* __restrict__ eo,
    const float* __restrict__ Wo,
    const int*   __restrict__ enc_len_w,
    float* __restrict__ out)
{
    const int b = blockIdx.y;
    const int chunk = blockIdx.x;
    const int tbase = chunk * CHUNK;
    // enc_len dtype auto-detect (JAX may canonicalize int64->int32):
    // lengths >= 1, so word[1]==0 iff buffer is little-endian int64.
    const bool is64 = (enc_len_w[1] == 0);
    const int len = is64 ? enc_len_w[2 * b] : enc_len_w[b];

    __shared__ __align__(16) float s_has[Hnum];
    __shared__ __align__(16) float s_wo[Hnum];
    __shared__ float s_ws[4];
    __shared__ float s_red[4];
    __shared__ float s_rinv;
    __shared__ int   s_last;

    const int tid  = threadIdx.x;
    const int warp = tid >> 5;
    const int lane = tid & 31;

    if (tbase < len) {
        {
            const float4* __restrict__ ha4 = (const float4*)(g_has + b * Hnum);
            const float4* __restrict__ wg4 = (const float4*)Wo;
            #pragma unroll
            for (int i = tid; i < Hnum / 4; i += ETHR) {
                ((float4*)s_has)[i] = ha4[i];
                ((float4*)s_wo)[i]  = wg4[i];
            }
        }
        __syncthreads();

        const float4* __restrict__ eo4 = (const float4*)eo;
        const int r0 = tbase + warp * 4;
        int nv = len - r0; nv = nv < 0 ? 0 : (nv > 4 ? 4 : nv);
        const size_t base = ((size_t)r0 * Bnum + b) * (Hnum / 4);
        const size_t tstride = (size_t)Bnum * (Hnum / 4);   // 4096 float4

        float acc0 = 0.f, acc1 = 0.f, acc2 = 0.f, acc3 = 0.f;
        float wsum = 0.f;

        if (nv == 4) {
            // fast path: 4 rows interleaved, branch-free
            #pragma unroll
            for (int j = 0; j < 4; j++) {
                const int k4 = j * 32 + lane;
                float4 hs = ((const float4*)s_has)[k4];
                float4 wo = ((const float4*)s_wo)[k4];
                float4 e0 = __ldcs(&eo4[base + 0 * tstride + k4]);
                float4 e1 = __ldcs(&eo4[base + 1 * tstride + k4]);
                float4 e2 = __ldcs(&eo4[base + 2 * tstride + k4]);
                float4 e3 = __ldcs(&eo4[base + 3 * tstride + k4]);

                acc0 = fmaf(tanha(e0.x + hs.x), wo.x, acc0);
                acc1 = fmaf(tanha(e1.x + hs.x), wo.x, acc1);
                acc2 = fmaf(tanha(e2.x + hs.x), wo.x, acc2);
                acc3 = fmaf(tanha(e3.x + hs.x), wo.x, acc3);

                acc0 = fmaf(tanha(e0.y + hs.y), wo.y, acc0);
                acc1 = fmaf(tanha(e1.y + hs.y), wo.y, acc1);
                acc2 = fmaf(tanha(e2.y + hs.y), wo.y, acc2);
                acc3 = fmaf(tanha(e3.y + hs.y), wo.y, acc3);

                acc0 = fmaf(tanha(e0.z + hs.z), wo.z, acc0);
                acc1 = fmaf(tanha(e1.z + hs.z), wo.z, acc1);
                acc2 = fmaf(tanha(e2.z + hs.z), wo.z, acc2);
                acc3 = fmaf(tanha(e3.z + hs.z), wo.z, acc3);

                acc0 = fmaf(tanha(e0.w + hs.w), wo.w, acc0);
                acc1 = fmaf(tanha(e1.w + hs.w), wo.w, acc1);
                acc2 = fmaf(tanha(e2.w + hs.w), wo.w, acc2);
                acc3 = fmaf(tanha(e3.w + hs.w), wo.w, acc3);
            }
        } else {
            // slow path: boundary chunk, per-row guarded (rare)
            #pragma unroll
            for (int r = 0; r < 4; r++) {
                if (r < nv) {
                    float a = 0.f;
                    #pragma unroll
                    for (int j = 0; j < 4; j++) {
                        const int k4 = j * 32 + lane;
                        float4 hs = ((const float4*)s_has)[k4];
                        float4 wo = ((const float4*)s_wo)[k4];
                        float4 e  = __ldcs(&eo4[base + (size_t)r * tstride + k4]);
                        a = fmaf(tanha(e.x + hs.x), wo.x, a);
                        a = fmaf(tanha(e.y + hs.y), wo.y, a);
                        a = fmaf(tanha(e.z + hs.z), wo.z, a);
                        a = fmaf(tanha(e.w + hs.w), wo.w, a);
                    }
                    if (r == 0) acc0 = a; else if (r == 1) acc1 = a;
                    else if (r == 2) acc2 = a; else acc3 = a;
                }
            }
        }

        // one reduction tail for all 4 rows (independent butterflies -> ILP)
        #pragma unroll
        for (int off = 16; off; off >>= 1) {
            acc0 += __shfl_xor_sync(0xffffffffu, acc0, off);
            acc1 += __shfl_xor_sync(0xffffffffu, acc1, off);
            acc2 += __shfl_xor_sync(0xffffffffu, acc2, off);
            acc3 += __shfl_xor_sync(0xffffffffu, acc3, off);
        }
        if (lane == 0) {
            float* __restrict__ prow = &g_p[b * Tnum + r0];
            // no-max exp is safe: |energy| <= sum|Wo| ~ 18 << fp32 exp range
            float p0 = (nv > 0) ? ex2a(acc0 * LOG2E) : 0.f;
            float p1 = (nv > 1) ? ex2a(acc1 * LOG2E) : 0.f;
            float p2 = (nv > 2) ? ex2a(acc2 * LOG2E) : 0.f;
            float p3 = (nv > 3) ? ex2a(acc3 * LOG2E) : 0.f;
            prow[0] = p0; prow[1] = p1; prow[2] = p2; prow[3] = p3;
            wsum = (p0 + p1) + (p2 + p3);
            s_ws[warp] = wsum;
        }
        __syncthreads();
        if (tid == 0) {
            g_psum[b * NCHUNK + chunk] =
                (s_ws[0] + s_ws[1]) + (s_ws[2] + s_ws[3]);
        }
    } else {
        // fully masked chunk: zeros, no eo traffic
        if (tid < CHUNK / 4)
            ((float4*)&g_p[b * Tnum + tbase])[tid] = make_float4(0.f, 0.f, 0.f, 0.f);
        if (tid == 0) g_psum[b * NCHUNK + chunk] = 0.f;
    }

    // ---- threadfence-reduction handoff: last block of this b normalizes ----
    __threadfence();
    if (tid == 0)
        s_last = (atomicAdd(&g_done[b], 1u) == NCHUNK - 1);
    __syncthreads();
    if (!s_last) return;

    {
        float v = g_psum[b * NCHUNK + tid];   // 128 partials, 128 threads
        #pragma unroll
        for (int off = 16; off; off >>= 1)
            v += __shfl_xor_sync(0xffffffffu, v, off);
        if (lane == 0) s_red[warp] = v;
    }
    __syncthreads();
    if (tid == 0)
        s_rinv = 1.0f / ((s_red[0] + s_red[1]) + (s_red[2] + s_red[3]));
    __syncthreads();
    const float rinv = s_rinv;

    const float4* __restrict__ p4 = (const float4*)&g_p[b * Tnum];
    float4* __restrict__ o4 = (float4*)&out[b * Tnum];
    #pragma unroll
    for (int i = tid; i < Tnum / 4; i += ETHR) {
        float4 p = p4[i];
        float4 o;
        o.x = p.x * rinv; o.y = p.y * rinv; o.z = p.z * rinv; o.w = p.w * rinv;
        o4[i] = o;
    }
    if (tid == 0) g_done[b] = 0u;   // reset for next graph replay
}

// ---------------------------------------------------------------------------
extern "C" void kernel_launch(void* const* d_in, const int* in_sizes, int n_in,
                              void* d_out, int out_size)
{
    const float* hidden  = (const float*)d_in[0];      // [L,B,H]
    const float* eo      = (const float*)d_in[1];      // [T,B,H]
    const int*   enc_len = (const int*)d_in[2];        // [B] int32/int64 (auto-detect)
    const float* Wh      = (const float*)d_in[3];      // [H,H]
    const float* bh      = (const float*)d_in[4];      // [H]
    const float* Wo      = (const float*)d_in[5];      // [1,H]
    // d_in[6] = bo: uniform additive constant -> cancels in softmax, unused.
    float* out = (float*)d_out;                         // [B,T,1]

    proj_kernel<<<Hnum / 8, 256>>>(hidden, Wh, bh);
    energy_kernel<<<dim3(NCHUNK, Bnum), ETHR>>>(eo, Wo, enc_len, out);
}